// round 5
// baseline (speedup 1.0000x reference)
#include <cuda_runtime.h>

// TCL-without-parameters loss, GB300 sm_103a.
// score[b,c] = 0.5*||center_c||^2 - f_b . center_c   (0.5||f||^2 cancels in pos-neg)
// loss = mean relu(score[lab] + 5 - min_{c!=lab} score[c])

#define MARGIN_F 5.0f

constexpr int D      = 512;   // feature dim
constexpr int C      = 21;    // num classes
constexpr int TPB    = 128;   // threads per block (4 warps)
constexpr int RPT    = 2;     // rows per thread
constexpr int RPB    = TPB * RPT;        // 256 rows per block
constexpr int CHUNK  = 16;    // columns staged per chunk
constexpr int SROW   = CHUNK + 4;        // padded smem row stride (floats): 20 floats = 80B
constexpr int NCHUNK = D / CHUNK;        // 32
constexpr int STAGES = 3;     // cp.async ring depth

__device__ float g_partials[1024];
__device__ unsigned int g_counter = 0;

__device__ __forceinline__ unsigned smem_u32(const void* p) {
    return (unsigned)__cvta_generic_to_shared(p);
}
__device__ __forceinline__ void cp16(void* s, const void* g) {
    asm volatile("cp.async.cg.shared.global [%0], [%1], 16;" :: "r"(smem_u32(s)), "l"(g));
}
__device__ __forceinline__ void cp_commit() { asm volatile("cp.async.commit_group;"); }
template <int N>
__device__ __forceinline__ void cp_wait() { asm volatile("cp.async.wait_group %0;" :: "n"(N)); }

// packed fp32x2 FMA (Blackwell): d = a*b + d, two independent fp32 lanes
__device__ __forceinline__ void fma2(unsigned long long& d, unsigned long long a, unsigned long long b) {
    asm("fma.rn.f32x2 %0, %1, %2, %0;" : "+l"(d) : "l"(a), "l"(b));
}

__global__ __launch_bounds__(TPB, 2)
void tcl_main_kernel(const float* __restrict__ feat,
                     const float* __restrict__ centers,
                     const void* __restrict__ labels,
                     float* __restrict__ out,
                     int B, int nblocks) {
    extern __shared__ float smem[];
    float* cen   = smem;                 // C*D floats (row-major, broadcast reads)
    float* c2    = cen + C * D;          // 32 floats (0.5*||c||^2)
    float* stage = c2 + 32;              // STAGES * RPB * SROW floats

    const int tid  = threadIdx.x;
    const int row0 = blockIdx.x * RPB;

    __shared__ int lab_is_i64;
    __shared__ unsigned int is_last;
    __shared__ float wsum[4];

    // ---- prologue: prefetch chunks 0 and 1 (coalesced cp.async) ----
    const float* fsrc = feat + (size_t)row0 * D;
    #pragma unroll
    for (int pc = 0; pc < 2; pc++) {
        float* dst = stage + pc * RPB * SROW;
        #pragma unroll
        for (int i = 0; i < RPB * (CHUNK / 4) / TPB; i++) {   // 8 iters
            int idx = tid + i * TPB;
            int r   = idx >> 2;           // idx / (CHUNK/4)
            int c4  = idx & 3;
            cp16(&dst[r * SROW + c4 * 4], fsrc + (size_t)r * D + pc * CHUNK + c4 * 4);
        }
        cp_commit();
    }

    // ---- label dtype sniff: int64 labels (<2^32) have all-zero odd int32 words ----
    if (tid == 0) {
        const int* lw = (const int*)labels;
        int i64 = 1;
        #pragma unroll 8
        for (int i = 1; i < 128; i += 2)
            if (lw[i] != 0) { i64 = 0; break; }
        lab_is_i64 = i64;
    }

    // ---- load centers into smem (L2-resident after first wave) ----
    for (int i = tid; i < C * D / 4; i += TPB)
        ((float4*)cen)[i] = ((const float4*)centers)[i];
    __syncthreads();

    // 0.5*||center_c||^2 (tiny, once per block; result needed only in epilogue,
    // visibility guaranteed by the per-chunk barriers)
    if (tid < C) {
        float s = 0.f;
        const float4* cv4 = (const float4*)(cen + tid * D);
        #pragma unroll 8
        for (int k = 0; k < D / 4; k++) {
            float4 v = cv4[k];
            s = fmaf(v.x, v.x, s); s = fmaf(v.y, v.y, s);
            s = fmaf(v.z, v.z, s); s = fmaf(v.w, v.w, s);
        }
        c2[tid] = 0.5f * s;
    }

    // packed accumulators: acc[c][r] holds (even-col partial, odd-col partial)
    unsigned long long acc[C][RPT];
    #pragma unroll
    for (int c = 0; c < C; c++)
        #pragma unroll
        for (int r = 0; r < RPT; r++) acc[c][r] = 0ull;

    // ---- main loop: 3-stage ring, ONE barrier per chunk ----
    for (int ch = 0; ch < NCHUNK; ch++) {
        cp_wait<1>();      // chunk ch has landed (only the newest group may be pending)
        __syncthreads();   // all warps done with buffer (ch+2)%3 (last used at ch-1)

        if (ch + 2 < NCHUNK) {
            float* dst = stage + ((ch + 2) % STAGES) * RPB * SROW;
            const float* src = fsrc + (ch + 2) * CHUNK;
            #pragma unroll
            for (int i = 0; i < RPB * (CHUNK / 4) / TPB; i++) {
                int idx = tid + i * TPB;
                int r   = idx >> 2;
                int c4  = idx & 3;
                cp16(&dst[r * SROW + c4 * 4], src + (size_t)r * D + c4 * 4);
            }
        }
        cp_commit();       // always commit (possibly empty) to keep group counting sound

        const float* buf = stage + (ch % STAGES) * RPB * SROW;
        const int kbase = ch * CHUNK;
        #pragma unroll
        for (int kk = 0; kk < CHUNK; kk += 4) {
            ulonglong2 f[RPT];
            #pragma unroll
            for (int r = 0; r < RPT; r++)
                f[r] = *(const ulonglong2*)&buf[(tid + r * TPB) * SROW + kk];  // LDS.128, conflict-free
            const float* cc = cen + kbase + kk;
            #pragma unroll
            for (int c = 0; c < C; c++) {
                ulonglong2 cv = *(const ulonglong2*)&cc[c * D];  // broadcast LDS.128
                fma2(acc[c][0], f[0].x, cv.x);
                fma2(acc[c][0], f[0].y, cv.y);
                fma2(acc[c][1], f[1].x, cv.x);
                fma2(acc[c][1], f[1].y, cv.y);
            }
        }
    }

    // ---- epilogue: per-row margin loss ----
    const int use64 = lab_is_i64;
    float local = 0.f;
    #pragma unroll
    for (int r = 0; r < RPT; r++) {
        int row = row0 + tid + r * TPB;
        int lab = use64 ? (int)((const long long*)labels)[row]
                        : ((const int*)labels)[row];
        float pos = 0.f, neg = 3.0e38f;
        #pragma unroll
        for (int c = 0; c < C; c++) {
            float lo = __uint_as_float((unsigned)(acc[c][r] & 0xffffffffu));
            float hi = __uint_as_float((unsigned)(acc[c][r] >> 32));
            float s  = c2[c] - (lo + hi);
            if (c == lab) pos = s;
            else          neg = fminf(neg, s);
        }
        local += fmaxf(0.f, pos + MARGIN_F - neg);
    }

    // ---- block reduce (4 warps) ----
    #pragma unroll
    for (int o = 16; o; o >>= 1) local += __shfl_down_sync(0xffffffffu, local, o);
    if ((tid & 31) == 0) wsum[tid >> 5] = local;
    __syncthreads();
    if (tid == 0) {
        g_partials[blockIdx.x] = wsum[0] + wsum[1] + wsum[2] + wsum[3];
        __threadfence();
        unsigned int old = atomicAdd(&g_counter, 1u);
        is_last = (old == (unsigned)(nblocks - 1)) ? 1u : 0u;
    }
    __syncthreads();

    // ---- last block folds the partials (no second launch) ----
    if (is_last) {
        float v = 0.f;
        for (int i = tid; i < nblocks; i += TPB) v += g_partials[i];
        #pragma unroll
        for (int o = 16; o; o >>= 1) v += __shfl_down_sync(0xffffffffu, v, o);
        if ((tid & 31) == 0) wsum[tid >> 5] = v;
        __syncthreads();
        if (tid == 0) {
            out[0] = (wsum[0] + wsum[1] + wsum[2] + wsum[3]) / (float)B;
            g_counter = 0;   // reset for next (graph-replayed) launch
        }
    }
}

extern "C" void kernel_launch(void* const* d_in, const int* in_sizes, int n_in,
                              void* d_out, int out_size) {
    // Identify inputs by element count: centers = C*D; labels = B; features = B*D.
    const float* cen = nullptr;
    for (int i = 0; i < n_in; i++)
        if (in_sizes[i] == C * D) cen = (const float*)d_in[i];

    int big = -1, small = -1;
    for (int i = 0; i < n_in; i++) {
        if ((const float*)d_in[i] == cen) continue;
        if (big < 0 || in_sizes[i] > in_sizes[big]) { small = big; big = i; }
        else small = i;
    }
    const float* feat = (const float*)d_in[big];
    const void*  lab  = d_in[small];
    int B = in_sizes[small];           // 65536

    int grid = B / RPB;                // 256 -> single wave, all blocks resident

    size_t smem_bytes = (size_t)(C * D + 32 + STAGES * RPB * SROW) * sizeof(float); // ~103 KB
    static int attr_set = 0;
    if (!attr_set) {
        cudaFuncSetAttribute(tcl_main_kernel, cudaFuncAttributeMaxDynamicSharedMemorySize,
                             (int)smem_bytes);
        attr_set = 1;
    }

    tcl_main_kernel<<<grid, TPB, smem_bytes>>>(feat, cen, lab, (float*)d_out, B, grid);
}

// round 6
// speedup vs baseline: 1.1898x; 1.1898x over previous
#include <cuda_runtime.h>

// TCL-without-parameters loss, GB300 sm_103a.
// score[b,c] = 0.5*||center_c||^2 - f_b . center_c   (0.5||f||^2 cancels in pos-neg)
// loss = mean relu(score[lab] + 5 - min_{c!=lab} score[c])

#define MARGIN_F 5.0f

constexpr int D      = 512;   // feature dim
constexpr int C      = 21;    // num classes
constexpr int TPB    = 256;   // threads per block (8 warps)
constexpr int RPT    = 1;     // rows per thread
constexpr int RPB    = TPB * RPT;        // 256 rows per block
constexpr int CHUNK  = 16;    // columns staged per chunk
constexpr int SROW   = CHUNK + 4;        // padded smem row stride (floats): 20 floats = 80B
constexpr int NCHUNK = D / CHUNK;        // 32
constexpr int STAGES = 3;     // cp.async ring depth
constexpr int CG1    = 11;    // class group 1 size (register-pressure split)
constexpr int CG2    = C - CG1;          // 10

__device__ float g_partials[1024];
__device__ unsigned int g_counter = 0;

__device__ __forceinline__ unsigned smem_u32(const void* p) {
    return (unsigned)__cvta_generic_to_shared(p);
}
__device__ __forceinline__ void cp16(void* s, const void* g) {
    asm volatile("cp.async.cg.shared.global [%0], [%1], 16;" :: "r"(smem_u32(s)), "l"(g));
}
__device__ __forceinline__ void cp_commit() { asm volatile("cp.async.commit_group;"); }
template <int N>
__device__ __forceinline__ void cp_wait() { asm volatile("cp.async.wait_group %0;" :: "n"(N)); }

// packed fp32x2 FMA (Blackwell): d = a*b + d, two independent fp32 lanes
__device__ __forceinline__ void fma2(unsigned long long& d, unsigned long long a, unsigned long long b) {
    asm("fma.rn.f32x2 %0, %1, %2, %0;" : "+l"(d) : "l"(a), "l"(b));
}

__global__ __launch_bounds__(TPB, 2)
void tcl_main_kernel(const float* __restrict__ feat,
                     const float* __restrict__ centers,
                     const void* __restrict__ labels,
                     float* __restrict__ out,
                     int B, int nblocks) {
    extern __shared__ float smem[];
    float* cen   = smem;                 // C*D floats (row-major, broadcast reads)
    float* c2    = cen + C * D;          // 32 floats (0.5*||c||^2)
    float* stage = c2 + 32;              // STAGES * RPB * SROW floats

    const int tid  = threadIdx.x;
    const int row0 = blockIdx.x * RPB;

    __shared__ int lab_is_i64;
    __shared__ unsigned int is_last;
    __shared__ float wsum[TPB / 32];

    // ---- prologue: prefetch chunks 0 and 1 (coalesced cp.async) ----
    const float* fsrc = feat + (size_t)row0 * D;
    #pragma unroll
    for (int pc = 0; pc < 2; pc++) {
        float* dst = stage + pc * RPB * SROW;
        #pragma unroll
        for (int i = 0; i < RPB * (CHUNK / 4) / TPB; i++) {   // 4 iters
            int idx = tid + i * TPB;
            int r   = idx >> 2;
            int c4  = idx & 3;
            cp16(&dst[r * SROW + c4 * 4], fsrc + (size_t)r * D + pc * CHUNK + c4 * 4);
        }
        cp_commit();
    }

    // ---- label dtype sniff: int64 labels (<2^32) have all-zero odd int32 words ----
    if (tid == 0) {
        const int* lw = (const int*)labels;
        int i64 = 1;
        #pragma unroll 8
        for (int i = 1; i < 128; i += 2)
            if (lw[i] != 0) { i64 = 0; break; }
        lab_is_i64 = i64;
    }

    // ---- load centers into smem (L2-resident after first wave) ----
    for (int i = tid; i < C * D / 4; i += TPB)
        ((float4*)cen)[i] = ((const float4*)centers)[i];
    __syncthreads();

    // 0.5*||center_c||^2 (tiny, once per block; visibility via per-chunk barriers)
    if (tid < C) {
        float s = 0.f;
        const float4* cv4 = (const float4*)(cen + tid * D);
        #pragma unroll 8
        for (int k = 0; k < D / 4; k++) {
            float4 v = cv4[k];
            s = fmaf(v.x, v.x, s); s = fmaf(v.y, v.y, s);
            s = fmaf(v.z, v.z, s); s = fmaf(v.w, v.w, s);
        }
        c2[tid] = 0.5f * s;
    }

    // packed accumulators: acc[c] = (even-col partial, odd-col partial) for this row
    unsigned long long acc[C];
    #pragma unroll
    for (int c = 0; c < C; c++) acc[c] = 0ull;

    // ---- main loop: 3-stage ring, ONE barrier per chunk ----
    for (int ch = 0; ch < NCHUNK; ch++) {
        cp_wait<1>();      // chunk ch has landed
        __syncthreads();   // all warps done with buffer (ch+2)%3 (last used at ch-1)

        if (ch + 2 < NCHUNK) {
            float* dst = stage + ((ch + 2) % STAGES) * RPB * SROW;
            const float* src = fsrc + (ch + 2) * CHUNK;
            #pragma unroll
            for (int i = 0; i < RPB * (CHUNK / 4) / TPB; i++) {
                int idx = tid + i * TPB;
                int r   = idx >> 2;
                int c4  = idx & 3;
                cp16(&dst[r * SROW + c4 * 4], src + (size_t)r * D + c4 * 4);
            }
        }
        cp_commit();       // always commit (possibly empty) to keep group counting sound

        const float* rowbuf = stage + (ch % STAGES) * RPB * SROW + tid * SROW;
        const int kbase = ch * CHUNK;
        #pragma unroll
        for (int kk = 0; kk < CHUNK; kk += 4) {
            ulonglong2 f = *(const ulonglong2*)&rowbuf[kk];     // own row, LDS.128 conflict-free
            const float* cc = cen + kbase + kk;

            // --- class group 1: load all, then .x phase, then .y phase (max ILP) ---
            ulonglong2 cv[CG1];
            #pragma unroll
            for (int c = 0; c < CG1; c++)
                cv[c] = *(const ulonglong2*)&cc[c * D];          // broadcast LDS.128
            #pragma unroll
            for (int c = 0; c < CG1; c++) fma2(acc[c], f.x, cv[c].x);
            #pragma unroll
            for (int c = 0; c < CG1; c++) fma2(acc[c], f.y, cv[c].y);

            // --- class group 2 ---
            ulonglong2 cw[CG2];
            #pragma unroll
            for (int c = 0; c < CG2; c++)
                cw[c] = *(const ulonglong2*)&cc[(CG1 + c) * D];
            #pragma unroll
            for (int c = 0; c < CG2; c++) fma2(acc[CG1 + c], f.x, cw[c].x);
            #pragma unroll
            for (int c = 0; c < CG2; c++) fma2(acc[CG1 + c], f.y, cw[c].y);
        }
    }

    // ---- epilogue: per-row margin loss ----
    const int use64 = lab_is_i64;
    float local = 0.f;
    {
        int row = row0 + tid;
        int lab = use64 ? (int)((const long long*)labels)[row]
                        : ((const int*)labels)[row];
        float pos = 0.f, neg = 3.0e38f;
        #pragma unroll
        for (int c = 0; c < C; c++) {
            float lo = __uint_as_float((unsigned)(acc[c] & 0xffffffffu));
            float hi = __uint_as_float((unsigned)(acc[c] >> 32));
            float s  = c2[c] - (lo + hi);
            if (c == lab) pos = s;
            else          neg = fminf(neg, s);
        }
        local = fmaxf(0.f, pos + MARGIN_F - neg);
    }

    // ---- block reduce (8 warps) ----
    #pragma unroll
    for (int o = 16; o; o >>= 1) local += __shfl_down_sync(0xffffffffu, local, o);
    if ((tid & 31) == 0) wsum[tid >> 5] = local;
    __syncthreads();
    if (tid == 0) {
        float bs = 0.f;
        #pragma unroll
        for (int w = 0; w < TPB / 32; w++) bs += wsum[w];
        g_partials[blockIdx.x] = bs;
        __threadfence();
        unsigned int old = atomicAdd(&g_counter, 1u);
        is_last = (old == (unsigned)(nblocks - 1)) ? 1u : 0u;
    }
    __syncthreads();

    // ---- last block folds the partials (no second launch) ----
    if (is_last) {
        float v = 0.f;
        for (int i = tid; i < nblocks; i += TPB) v += g_partials[i];
        #pragma unroll
        for (int o = 16; o; o >>= 1) v += __shfl_down_sync(0xffffffffu, v, o);
        if ((tid & 31) == 0) wsum[tid >> 5] = v;
        __syncthreads();
        if (tid == 0) {
            float t = 0.f;
            #pragma unroll
            for (int w = 0; w < TPB / 32; w++) t += wsum[w];
            out[0] = t / (float)B;
            g_counter = 0;   // reset for next (graph-replayed) launch
        }
    }
}

extern "C" void kernel_launch(void* const* d_in, const int* in_sizes, int n_in,
                              void* d_out, int out_size) {
    // Identify inputs by element count: centers = C*D; labels = B; features = B*D.
    const float* cen = nullptr;
    for (int i = 0; i < n_in; i++)
        if (in_sizes[i] == C * D) cen = (const float*)d_in[i];

    int big = -1, small = -1;
    for (int i = 0; i < n_in; i++) {
        if ((const float*)d_in[i] == cen) continue;
        if (big < 0 || in_sizes[i] > in_sizes[big]) { small = big; big = i; }
        else small = i;
    }
    const float* feat = (const float*)d_in[big];
    const void*  lab  = d_in[small];
    int B = in_sizes[small];           // 65536

    int grid = B / RPB;                // 256 -> single wave, all blocks resident

    size_t smem_bytes = (size_t)(C * D + 32 + STAGES * RPB * SROW) * sizeof(float); // ~102 KB
    static int attr_set = 0;
    if (!attr_set) {
        cudaFuncSetAttribute(tcl_main_kernel, cudaFuncAttributeMaxDynamicSharedMemorySize,
                             (int)smem_bytes);
        attr_set = 1;
    }

    tcl_main_kernel<<<grid, TPB, smem_bytes>>>(feat, cen, lab, (float*)d_out, B, grid);
}

// round 7
// speedup vs baseline: 1.2573x; 1.0568x over previous
#include <cuda_runtime.h>

// TCL-without-parameters loss, GB300 sm_103a.
// score[b,c] = 0.5*||center_c||^2 - f_b . center_c   (0.5||f||^2 cancels in pos-neg)
// loss = mean relu(score[lab] + 5 - min_{c!=lab} score[c])
//
// R7 design: 4 rows/thread x half-K/thread (split-K pairs), col-packed f32x2
// accumulators, centers broadcast from smem, phased class groups (7/7/7).

#define MARGIN_F 5.0f

constexpr int D      = 512;
constexpr int C      = 21;
constexpr int TPB    = 128;   // 64 row-threads x 2 K-halves
constexpr int RT     = 64;    // row-threads per block
constexpr int RPT    = 4;     // rows per thread
constexpr int RPB    = RT * RPT;          // 256 rows per block
constexpr int HALFK  = D / 2;             // 256 cols per thread
constexpr int CHUNK  = 8;     // cols staged per chunk PER HALF (16 total)
constexpr int SROW   = 20;    // smem floats per staged row (16 data + 4 pad)
constexpr int NCHUNK = HALFK / CHUNK;     // 32
constexpr int STAGES = 3;
constexpr int CGRP   = 7;     // class group size (21 = 3 x 7)

__device__ float g_partials[1024];
__device__ unsigned int g_counter = 0;

__device__ __forceinline__ unsigned smem_u32(const void* p) {
    return (unsigned)__cvta_generic_to_shared(p);
}
__device__ __forceinline__ void cp16(void* s, const void* g) {
    asm volatile("cp.async.cg.shared.global [%0], [%1], 16;" :: "r"(smem_u32(s)), "l"(g));
}
__device__ __forceinline__ void cp_commit() { asm volatile("cp.async.commit_group;"); }
template <int N>
__device__ __forceinline__ void cp_wait() { asm volatile("cp.async.wait_group %0;" :: "n"(N)); }

// packed fp32x2 FMA (Blackwell): d = a*b + d, two independent fp32 lanes
__device__ __forceinline__ void fma2(unsigned long long& d, unsigned long long a, unsigned long long b) {
    asm("fma.rn.f32x2 %0, %1, %2, %0;" : "+l"(d) : "l"(a), "l"(b));
}

__global__ __launch_bounds__(TPB, 2)
void tcl_main_kernel(const float* __restrict__ feat,
                     const float* __restrict__ centers,
                     const void* __restrict__ labels,
                     float* __restrict__ out,
                     int B, int nblocks) {
    extern __shared__ float smem[];
    float* cen   = smem;                  // C*D floats
    float* c2    = cen + C * D;           // 32 floats (0.5*||c||^2)
    float* stage = c2 + 32;               // STAGES * RPB * SROW floats

    const int tid  = threadIdx.x;
    const int rt   = tid & 63;            // row-thread id
    const int kh   = tid >> 6;            // K-half (0 or 1)
    const int row0 = blockIdx.x * RPB;

    __shared__ int lab_is_i64;
    __shared__ unsigned int is_last;
    __shared__ float wsum[TPB / 32];

    // ---- prologue: prefetch chunks 0,1 for both halves (coalesced cp.async) ----
    // smem row layout per staged row: cols [0..7] = half0, cols [8..15] = half1.
    const float* fblk = feat + (size_t)row0 * D;
    #pragma unroll
    for (int pc = 0; pc < 2; pc++) {
        float* dst = stage + pc * RPB * SROW;
        #pragma unroll
        for (int i = 0; i < RPB * 4 / TPB; i++) {   // 1024 cp16 / 128 thr = 8
            int idx = tid + i * TPB;
            int r   = idx >> 2;          // 0..255
            int rem = idx & 3;
            int h   = rem >> 1;          // half
            int q   = rem & 1;           // quad within half's 8 cols
            cp16(&dst[r * SROW + h * 8 + q * 4],
                 fblk + (size_t)r * D + h * HALFK + pc * CHUNK + q * 4);
        }
        cp_commit();
    }

    // ---- label dtype sniff: int64 labels (<2^32) have all-zero odd int32 words ----
    if (tid == 0) {
        const int* lw = (const int*)labels;
        int i64 = 1;
        #pragma unroll 8
        for (int i = 1; i < 128; i += 2)
            if (lw[i] != 0) { i64 = 0; break; }
        lab_is_i64 = i64;
    }

    // ---- centers into smem ----
    for (int i = tid; i < C * D / 4; i += TPB)
        ((float4*)cen)[i] = ((const float4*)centers)[i];
    __syncthreads();

    if (tid < C) {
        float s = 0.f;
        const float4* cv4 = (const float4*)(cen + tid * D);
        #pragma unroll 8
        for (int k = 0; k < D / 4; k++) {
            float4 v = cv4[k];
            s = fmaf(v.x, v.x, s); s = fmaf(v.y, v.y, s);
            s = fmaf(v.z, v.z, s); s = fmaf(v.w, v.w, s);
        }
        c2[tid] = 0.5f * s;
    }

    // packed accumulators: acc[c][r] = (cols k, k+1 partial sums) for row r of this thread
    unsigned long long acc[C][RPT];
    #pragma unroll
    for (int c = 0; c < C; c++)
        #pragma unroll
        for (int r = 0; r < RPT; r++) acc[c][r] = 0ull;

    const int colbase = kh * HALFK;       // this thread's K-half origin in centers
    const int smemcol = kh * 8;           // this half's col offset in staged rows

    // ---- main loop ----
    for (int ch = 0; ch < NCHUNK; ch++) {
        cp_wait<1>();
        __syncthreads();

        if (ch + 2 < NCHUNK) {
            float* dst = stage + ((ch + 2) % STAGES) * RPB * SROW;
            const float* src0 = fblk + (size_t)(ch + 2) * CHUNK;
            #pragma unroll
            for (int i = 0; i < RPB * 4 / TPB; i++) {
                int idx = tid + i * TPB;
                int r   = idx >> 2;
                int rem = idx & 3;
                int h   = rem >> 1;
                int q   = rem & 1;
                cp16(&dst[r * SROW + h * 8 + q * 4],
                     src0 + (size_t)r * D + h * HALFK + q * 4);
            }
        }
        cp_commit();

        const float* buf = stage + (ch % STAGES) * RPB * SROW + smemcol;
        #pragma unroll
        for (int s4 = 0; s4 < CHUNK; s4 += 4) {      // 2 micro-steps of 4 cols
            // feature loads: rows rt, rt+64, rt+128, rt+192 -> conflict-free LDS.128
            ulonglong2 f[RPT];
            #pragma unroll
            for (int r = 0; r < RPT; r++)
                f[r] = *(const ulonglong2*)&buf[(rt + r * RT) * SROW + s4];
            const float* cc = cen + colbase + ch * CHUNK + s4;

            #pragma unroll
            for (int g = 0; g < C / CGRP; g++) {     // 3 class groups of 7
                ulonglong2 cv[CGRP];
                #pragma unroll
                for (int j = 0; j < CGRP; j++)
                    cv[j] = *(const ulonglong2*)&cc[(g * CGRP + j) * D];  // broadcast LDS.128
                // phase 1: low u64 (cols s4, s4+1)
                #pragma unroll
                for (int j = 0; j < CGRP; j++)
                    #pragma unroll
                    for (int r = 0; r < RPT; r++)
                        fma2(acc[g * CGRP + j][r], f[r].x, cv[j].x);
                // phase 2: high u64 (cols s4+2, s4+3)
                #pragma unroll
                for (int j = 0; j < CGRP; j++)
                    #pragma unroll
                    for (int r = 0; r < RPT; r++)
                        fma2(acc[g * CGRP + j][r], f[r].y, cv[j].y);
            }
        }
    }

    // ---- split-K combine: half-1 threads publish partials via smem ----
    __syncthreads();                       // all compute done; stage reusable
    unsigned long long* comb = (unsigned long long*)stage;   // 64 * 84 u64 = 43KB <= stage
    if (kh == 1) {
        #pragma unroll
        for (int c = 0; c < C; c++)
            #pragma unroll
            for (int r = 0; r < RPT; r++)
                comb[rt * (C * RPT) + c * RPT + r] = acc[c][r];
    }
    __syncthreads();

    // ---- epilogue: half-0 threads own 4 rows each ----
    const int use64 = lab_is_i64;
    float local = 0.f;
    if (kh == 0) {
        #pragma unroll
        for (int r = 0; r < RPT; r++) {
            int row = row0 + rt + r * RT;
            int lab = use64 ? (int)((const long long*)labels)[row]
                            : ((const int*)labels)[row];
            float pos = 0.f, neg = 3.0e38f;
            #pragma unroll
            for (int c = 0; c < C; c++) {
                unsigned long long a = acc[c][r];
                unsigned long long p = comb[rt * (C * RPT) + c * RPT + r];
                float lo = __uint_as_float((unsigned)(a & 0xffffffffu))
                         + __uint_as_float((unsigned)(p & 0xffffffffu));
                float hi = __uint_as_float((unsigned)(a >> 32))
                         + __uint_as_float((unsigned)(p >> 32));
                float s  = c2[c] - (lo + hi);
                if (c == lab) pos = s;
                else          neg = fminf(neg, s);
            }
            local += fmaxf(0.f, pos + MARGIN_F - neg);
        }
    }

    // ---- block reduce ----
    #pragma unroll
    for (int o = 16; o; o >>= 1) local += __shfl_down_sync(0xffffffffu, local, o);
    if ((tid & 31) == 0) wsum[tid >> 5] = local;
    __syncthreads();
    if (tid == 0) {
        float bs = 0.f;
        #pragma unroll
        for (int w = 0; w < TPB / 32; w++) bs += wsum[w];
        g_partials[blockIdx.x] = bs;
        __threadfence();
        unsigned int old = atomicAdd(&g_counter, 1u);
        is_last = (old == (unsigned)(nblocks - 1)) ? 1u : 0u;
    }
    __syncthreads();

    if (is_last) {
        float v = 0.f;
        for (int i = tid; i < nblocks; i += TPB) v += g_partials[i];
        #pragma unroll
        for (int o = 16; o; o >>= 1) v += __shfl_down_sync(0xffffffffu, v, o);
        if ((tid & 31) == 0) wsum[tid >> 5] = v;
        __syncthreads();
        if (tid == 0) {
            float t = 0.f;
            #pragma unroll
            for (int w = 0; w < TPB / 32; w++) t += wsum[w];
            out[0] = t / (float)B;
            g_counter = 0;    // reset for next graph replay
        }
    }
}

extern "C" void kernel_launch(void* const* d_in, const int* in_sizes, int n_in,
                              void* d_out, int out_size) {
    const float* cen = nullptr;
    for (int i = 0; i < n_in; i++)
        if (in_sizes[i] == C * D) cen = (const float*)d_in[i];

    int big = -1, small = -1;
    for (int i = 0; i < n_in; i++) {
        if ((const float*)d_in[i] == cen) continue;
        if (big < 0 || in_sizes[i] > in_sizes[big]) { small = big; big = i; }
        else small = i;
    }
    const float* feat = (const float*)d_in[big];
    const void*  lab  = d_in[small];
    int B = in_sizes[small];              // 65536

    int grid = B / RPB;                   // 256

    size_t smem_bytes = (size_t)(C * D + 32 + STAGES * RPB * SROW) * sizeof(float); // ~104.6 KB
    static int attr_set = 0;
    if (!attr_set) {
        cudaFuncSetAttribute(tcl_main_kernel, cudaFuncAttributeMaxDynamicSharedMemorySize,
                             (int)smem_bytes);
        attr_set = 1;
    }

    tcl_main_kernel<<<grid, TPB, smem_bytes>>>(feat, cen, lab, (float*)d_out, B, grid);
}

// round 11
// speedup vs baseline: 1.8272x; 1.4533x over previous
#include <cuda_runtime.h>
#include <cuda.h>
#include <cstdint>

// TCL-without-parameters loss, GB300 sm_103a (compiled as compute_103).
// score[b,c] = 0.5*||center_c||^2 - f_b . center_c   (0.5||f||^2 cancels in pos-neg)
// loss = mean relu(score[lab] + 5 - min_{c!=lab} score[c])
//
// R9: TMA (cp.async.bulk.tensor.2d, SW128) feature staging + mma.sync tf32 compute.

#define MARGIN_F 5.0f

constexpr int D      = 512;
constexpr int C      = 21;
constexpr int NPAD   = 24;          // classes padded to 3 n-tiles of 8
constexpr int TILE_M = 128;
constexpr int KC     = 32;          // k-cols per chunk (32 f32 = 128B rows -> SW128 atom)
constexpr int NCH    = D / KC;      // 16
constexpr int S      = 8;           // stage ring depth
constexpr int TPB    = 288;         // warps 0-7 consumers, warp 8 TMA producer
constexpr int GRID   = 148;
constexpr int BS     = 516;         // padded B row stride (floats), conflict-free

constexpr int STAGE_BYTES = TILE_M * KC * 4;   // 16384

// dynamic smem byte offsets
constexpr int SM_FULL  = 0;                     // S mbars
constexpr int SM_EMPTY = 64;                    // S mbars
constexpr int SM_C2    = 128;                   // 32 floats
constexpr int SM_FLAG  = 256;                   // label dtype flag
constexpr int SM_WSUM  = 288;                   // 9 floats
constexpr int SM_B     = 512;                   // NPAD*BS floats (tf32 bits) = 49536B
constexpr int SM_A     = 50176;                 // 1024-aligned; S stages
constexpr int SMEM_TOTAL = SM_A + S * STAGE_BYTES;   // 181248

__device__ float g_partials[256];
__device__ unsigned int g_counter = 0;

// ---------- device helpers ----------
__device__ __forceinline__ uint32_t smem_u32(const void* p) {
    return (uint32_t)__cvta_generic_to_shared(p);
}
#define SW128(o) ((uint32_t)(o) ^ ((((uint32_t)(o)) >> 3) & 0x70u))

#define MBARRIER_INIT(addr, cnt) \
    asm volatile("mbarrier.init.shared.b64 [%0], %1;" :: "r"((uint32_t)(addr)), "r"((uint32_t)(cnt)) : "memory")
#define MBARRIER_ARRIVE(addr) \
    asm volatile("mbarrier.arrive.shared.b64 _, [%0];" :: "r"((uint32_t)(addr)) : "memory")
#define MBARRIER_EXPECT_TX(addr, bytes) \
    asm volatile("mbarrier.arrive.expect_tx.shared.b64 _, [%0], %1;" :: "r"((uint32_t)(addr)), "r"((uint32_t)(bytes)) : "memory")
#define FENCE_PROXY_ASYNC() asm volatile("fence.proxy.async.shared::cta;" ::: "memory")

#define MBARRIER_WAIT_PARITY(addr, par) do {                                        \
    uint32_t _mbar = (uint32_t)(addr);                                              \
    uint32_t _par  = (uint32_t)(par);                                               \
    uint32_t _done;                                                                 \
    asm volatile("{\n\t.reg .pred p;\n\t"                                           \
        "mbarrier.try_wait.parity.shared.b64 p, [%1], %2;\n\t"                      \
        "selp.b32 %0, 1, 0, p;\n\t}"                                                \
        : "=r"(_done) : "r"(_mbar), "r"(_par) : "memory");                          \
    if (!_done) {                                                                   \
        asm volatile("{\n\t.reg .pred P1;\n\t"                                      \
            "WAIT_LOOP_%=:\n\t"                                                     \
            "mbarrier.try_wait.parity.shared.b64 P1, [%0], %1;\n\t"                 \
            "@P1 bra.uni WAIT_DONE_%=;\n\t"                                         \
            "bra.uni WAIT_LOOP_%=;\n\t"                                             \
            "WAIT_DONE_%=:\n\t}"                                                    \
            :: "r"(_mbar), "r"(_par) : "memory");                                   \
    }                                                                               \
} while (0)

__device__ __forceinline__ uint32_t f2tf32(float x) {
    uint32_t r;
    asm("cvt.rna.tf32.f32 %0, %1;" : "=r"(r) : "f"(x));
    return r;
}

__device__ __forceinline__ void mma_tf32(float d[4], uint32_t a0, uint32_t a1,
                                         uint32_t a2, uint32_t a3,
                                         uint32_t b0, uint32_t b1) {
    asm volatile(
        "mma.sync.aligned.m16n8k8.row.col.f32.tf32.tf32.f32 "
        "{%0,%1,%2,%3}, {%4,%5,%6,%7}, {%8,%9}, {%0,%1,%2,%3};"
        : "+f"(d[0]), "+f"(d[1]), "+f"(d[2]), "+f"(d[3])
        : "r"(a0), "r"(a1), "r"(a2), "r"(a3), "r"(b0), "r"(b1));
}

// ---------- kernel ----------
__global__ __launch_bounds__(TPB, 1)
void tcl_mma_kernel(const __grid_constant__ CUtensorMap tmap,
                    const float* __restrict__ centers,
                    const void* __restrict__ labels,
                    float* __restrict__ out,
                    int Btot, int ntiles) {
    extern __shared__ __align__(1024) char smemc[];
    const uint32_t sb = smem_u32(smemc);
    const int tid = threadIdx.x, wid = tid >> 5, lane = tid & 31;
    const int q = lane & 3, g4 = lane >> 2;
    const int bid = blockIdx.x;

    __shared__ unsigned int is_last;

    if (tid == 0) {
        #pragma unroll
        for (int s = 0; s < S; s++) {
            MBARRIER_INIT(sb + SM_FULL  + s * 8, 1);   // completes via TMA tx
            MBARRIER_INIT(sb + SM_EMPTY + s * 8, 8);   // 8 consumer warps
        }
        FENCE_PROXY_ASYNC();                           // barriers visible to async proxy
        // label dtype sniff: int64 labels (<2^32) have all-zero odd int32 words
        const int* lw = (const int*)labels;
        int i64 = 1;
        for (int i = 1; i < 128; i += 2) if (lw[i] != 0) { i64 = 0; break; }
        *(int*)(smemc + SM_FLAG) = i64;
    }

    // ---- B: centers -> tf32 bits in padded smem; junk rows 21..23 zero ----
    uint32_t* Bt = (uint32_t*)(smemc + SM_B);
    for (int i = tid; i < NPAD * D; i += TPB) {
        int n = i >> 9, k = i & 511;
        float v = (n < C) ? centers[n * D + k] : 0.f;
        Bt[n * BS + k] = f2tf32(v);
    }
    // c2: 0.5*||center||^2 (fp32 exact); junk cols -> +huge (self-excluded from min)
    if (tid < 32) {
        float val = 1.0e30f;
        if (tid < C) {
            float s = 0.f;
            const float* cp = centers + tid * D;
            #pragma unroll 8
            for (int k = 0; k < D; k++) s = fmaf(cp[k], cp[k], s);
            val = 0.5f * s;
        }
        ((float*)(smemc + SM_C2))[tid] = val;
    }
    __syncthreads();

    const int use64 = *(const int*)(smemc + SM_FLAG);
    const float* c2s = (const float*)(smemc + SM_C2);
    float local = 0.f;

    if (wid == 8) {
        // ---------------- producer: one TMA per 16KB chunk ----------------
        if (lane == 0) {
            int st = 0, ph = 1;       // parity 1: first empty-wait passes on fresh barriers
            for (int t = bid; t < ntiles; t += GRID) {
                for (int ch = 0; ch < NCH; ch++) {
                    MBARRIER_WAIT_PARITY(sb + SM_EMPTY + st * 8, ph);
                    MBARRIER_EXPECT_TX(sb + SM_FULL + st * 8, STAGE_BYTES);
                    asm volatile(
                        "cp.async.bulk.tensor.2d.shared::cta.global.tile.mbarrier::complete_tx::bytes "
                        "[%0], [%1, {%2, %3}], [%4];"
                        :: "r"(sb + SM_A + st * STAGE_BYTES), "l"(&tmap),
                           "r"(ch * KC), "r"(t * TILE_M),
                           "r"(sb + SM_FULL + st * 8)
                        : "memory");
                    if (++st == S) { st = 0; ph ^= 1; }
                }
            }
        }
    } else {
        // ---------------- consumers: warp w owns rows [16w, 16w+16) of each tile ----
        const int r0 = wid * 16 + g4;      // fragment row (a0/a2), r1 = r0 + 8
        int st = 0, ph = 0;
        for (int t = bid; t < ntiles; t += GRID) {
            float d[3][4];
            #pragma unroll
            for (int nt = 0; nt < 3; nt++)
                #pragma unroll
                for (int e = 0; e < 4; e++) d[nt][e] = 0.f;

            for (int ch = 0; ch < NCH; ch++) {
                MBARRIER_WAIT_PARITY(sb + SM_FULL + st * 8, ph);
                const char* Ab = smemc + SM_A + st * STAGE_BYTES;
                #pragma unroll
                for (int ks = 0; ks < 4; ks++) {
                    const int ca = ks * 8 + q;     // col in chunk for a0/a1
                    uint32_t a0 = f2tf32(*(const float*)(Ab + SW128(r0 * 128 + ca * 4)));
                    uint32_t a1 = f2tf32(*(const float*)(Ab + SW128((r0 + 8) * 128 + ca * 4)));
                    uint32_t a2 = f2tf32(*(const float*)(Ab + SW128(r0 * 128 + (ca + 4) * 4)));
                    uint32_t a3 = f2tf32(*(const float*)(Ab + SW128((r0 + 8) * 128 + (ca + 4) * 4)));
                    const int k8 = ch * KC + ks * 8;
                    #pragma unroll
                    for (int nt = 0; nt < 3; nt++) {
                        uint32_t b0 = Bt[(nt * 8 + g4) * BS + k8 + q];
                        uint32_t b1 = Bt[(nt * 8 + g4) * BS + k8 + q + 4];
                        mma_tf32(d[nt], a0, a1, a2, a3, b0, b1);
                    }
                }
                __syncwarp();
                if (lane == 0) MBARRIER_ARRIVE(sb + SM_EMPTY + st * 8);
                if (++st == S) { st = 0; ph ^= 1; }
            }

            // ---- per-tile epilogue: rows rA = t*128 + r0, rB = rA + 8 ----
            const int rA = t * TILE_M + r0, rB = rA + 8;
            const int labA = use64 ? (int)((const long long*)labels)[rA]
                                   : ((const int*)labels)[rA];
            const int labB = use64 ? (int)((const long long*)labels)[rB]
                                   : ((const int*)labels)[rB];
            float posA = -3.0e38f, negA = 3.0e38f, posB = -3.0e38f, negB = 3.0e38f;
            #pragma unroll
            for (int nt = 0; nt < 3; nt++) {
                #pragma unroll
                for (int e = 0; e < 2; e++) {
                    const int col = nt * 8 + 2 * q + e;
                    const float c2v = c2s[col];
                    const float sA = c2v - d[nt][e];
                    const float sB = c2v - d[nt][2 + e];
                    if (col == labA) posA = sA; else negA = fminf(negA, sA);
                    if (col == labB) posB = sB; else negB = fminf(negB, sB);
                }
            }
            #pragma unroll
            for (int off = 1; off <= 2; off <<= 1) {
                posA = fmaxf(posA, __shfl_xor_sync(0xffffffffu, posA, off));
                negA = fminf(negA, __shfl_xor_sync(0xffffffffu, negA, off));
                posB = fmaxf(posB, __shfl_xor_sync(0xffffffffu, posB, off));
                negB = fminf(negB, __shfl_xor_sync(0xffffffffu, negB, off));
            }
            if (q == 0)
                local += fmaxf(0.f, posA + MARGIN_F - negA)
                       + fmaxf(0.f, posB + MARGIN_F - negB);
        }
    }

    // ---- block reduce (9 warps) + fused final reduction ----
    __syncthreads();
    float* wsum = (float*)(smemc + SM_WSUM);
    #pragma unroll
    for (int o = 16; o; o >>= 1) local += __shfl_down_sync(0xffffffffu, local, o);
    if (lane == 0) wsum[wid] = local;
    __syncthreads();
    if (tid == 0) {
        float bs = 0.f;
        #pragma unroll
        for (int w = 0; w < TPB / 32; w++) bs += wsum[w];
        g_partials[bid] = bs;
        __threadfence();
        unsigned int old = atomicAdd(&g_counter, 1u);
        is_last = (old == (unsigned)(gridDim.x - 1)) ? 1u : 0u;
    }
    __syncthreads();

    if (is_last) {
        float v = 0.f;
        for (int i = tid; i < (int)gridDim.x; i += TPB) v += g_partials[i];
        #pragma unroll
        for (int o = 16; o; o >>= 1) v += __shfl_down_sync(0xffffffffu, v, o);
        if (lane == 0) wsum[wid] = v;
        __syncthreads();
        if (tid == 0) {
            float tsum = 0.f;
            #pragma unroll
            for (int w = 0; w < TPB / 32; w++) tsum += wsum[w];
            out[0] = tsum / (float)Btot;
            g_counter = 0;     // reset for next graph replay
        }
    }
}

// ---------- host ----------
typedef CUresult (*PFN_encodeTiled)(CUtensorMap*, CUtensorMapDataType, cuuint32_t,
                                    void*, const cuuint64_t*, const cuuint64_t*,
                                    const cuuint32_t*, const cuuint32_t*,
                                    CUtensorMapInterleave, CUtensorMapSwizzle,
                                    CUtensorMapL2promotion, CUtensorMapFloatOOBfill);

extern "C" void kernel_launch(void* const* d_in, const int* in_sizes, int n_in,
                              void* d_out, int out_size) {
    // Identify inputs by element count: centers = C*D; labels = B; features = B*D.
    const float* cen = nullptr;
    for (int i = 0; i < n_in; i++)
        if (in_sizes[i] == C * D) cen = (const float*)d_in[i];

    int big = -1, small = -1;
    for (int i = 0; i < n_in; i++) {
        if ((const float*)d_in[i] == cen) continue;
        if (big < 0 || in_sizes[i] > in_sizes[big]) { small = big; big = i; }
        else small = i;
    }
    float*      feat = (float*)d_in[big];
    const void* lab  = d_in[small];
    int B = in_sizes[small];              // 65536
    int ntiles = B / TILE_M;              // 512

    // TMA tensormap via driver entry point (no -lcuda link needed)
    static PFN_encodeTiled encode_fn = nullptr;
    if (!encode_fn) {
        void* fn = nullptr;
        cudaDriverEntryPointQueryResult qr;
        cudaGetDriverEntryPoint("cuTensorMapEncodeTiled", &fn,
                                cudaEnableDefault, &qr);
        encode_fn = (PFN_encodeTiled)fn;
    }
    CUtensorMap tmap;
    {
        cuuint64_t dims[2]    = {(cuuint64_t)D, (cuuint64_t)B};
        cuuint64_t strides[1] = {(cuuint64_t)D * sizeof(float)};
        cuuint32_t box[2]     = {(cuuint32_t)KC, (cuuint32_t)TILE_M};
        cuuint32_t estr[2]    = {1, 1};
        encode_fn(&tmap, CU_TENSOR_MAP_DATA_TYPE_FLOAT32, 2, feat,
                  dims, strides, box, estr,
                  CU_TENSOR_MAP_INTERLEAVE_NONE, CU_TENSOR_MAP_SWIZZLE_128B,
                  CU_TENSOR_MAP_L2_PROMOTION_L2_128B,
                  CU_TENSOR_MAP_FLOAT_OOB_FILL_NONE);
    }

    static int attr_set = 0;
    if (!attr_set) {
        cudaFuncSetAttribute(tcl_mma_kernel, cudaFuncAttributeMaxDynamicSharedMemorySize,
                             SMEM_TOTAL);
        attr_set = 1;
    }

    tcl_mma_kernel<<<GRID, TPB, SMEM_TOTAL>>>(tmap, cen, lab, (float*)d_out, B, ntiles);
}